// round 6
// baseline (speedup 1.0000x reference)
#include <cuda_runtime.h>
#include <math.h>

#define BSZ    4
#define LSEQ   2048
#define DMODEL 1024
#define DINNER 2048
#define DSTATE 16
#define DTRANK 64
#define NTOK   (BSZ*LSEQ)        // 8192
#define TT     8
#define HH     16
#define WW     16
#define NFR    (BSZ*TT)          // 32
#define XDBLW  96
#define NOUT   (BSZ*LSEQ*DMODEL) // 8388608

// ---------------- scratch (static device globals; no allocation) -------------
__device__ float g_xcl [BSZ*DINNER*LSEQ];   // x  (B, D_INNER, L) channel-major
__device__ float g_zt  [BSZ*LSEQ*DINNER];   // z  (B, L, D_INNER)
__device__ float g_xct [BSZ*LSEQ*DINNER];   // conv(x) silu'd, (B, L, D_INNER)
__device__ float g_delta[BSZ*LSEQ*DINNER];  // (B, L, D_INNER)
__device__ float g_y   [BSZ*LSEQ*DINNER];   // (B, L, D_INNER)
__device__ float g_xdbl[NTOK*XDBLW];        // (B*L, 96) : dt_low | Bm | Cm
__device__ float g_feat[NFR*DINNER];        // (32, 2048)
__device__ float g_f   [DINNER];            // softmax(mean features)
__device__ float g_att [DINNER];
__device__ float g_attmax;
__device__ float g_Amax[DSTATE];
__device__ float g_Amin[DSTATE];
__device__ float g_A   [DINNER*DSTATE];     // final A = -exp(A_new)

// exact twiddles: cos/sin(2*pi*k/16), double-rounded to fp32
__constant__ float c_ct[16] = {
    1.0f, 0.92387953251128674f, 0.70710678118654752f, 0.38268343236508978f,
    0.0f, -0.38268343236508978f, -0.70710678118654752f, -0.92387953251128674f,
    -1.0f, -0.92387953251128674f, -0.70710678118654752f, -0.38268343236508978f,
    0.0f, 0.38268343236508978f, 0.70710678118654752f, 0.92387953251128674f};
__constant__ float c_st[16] = {
    0.0f, 0.38268343236508978f, 0.70710678118654752f, 0.92387953251128674f,
    1.0f, 0.92387953251128674f, 0.70710678118654752f, 0.38268343236508978f,
    0.0f, -0.38268343236508978f, -0.70710678118654752f, -0.92387953251128674f,
    -1.0f, -0.92387953251128674f, -0.70710678118654752f, -0.38268343236508978f};

// ---------------- GEMM: C[m,n] = sum_k A[m,k]*B[n,k]  (NT) -------------------
// MODE 0: plain store C[m*N+n]
// MODE 1: in_proj split: n<DINNER -> x_cl[b][n][l]; else -> z_t[b][l][n-DINNER]
// MODE 2: delta = softplus(acc + bias[n])
template<int MODE>
__global__ __launch_bounds__(256)
void gemm_nt(const float* __restrict__ A, int lda,
             const float* __restrict__ B, int ldb,
             float* __restrict__ C,
             int M, int N, int K,
             const float* __restrict__ bias,
             float* __restrict__ aux)
{
    __shared__ float As[16][68];
    __shared__ float Bs[16][68];
    const int t  = threadIdx.x;
    const int tx = t & 15, ty = t >> 4;
    const int m0 = blockIdx.y * 64, n0 = blockIdx.x * 64;
    const int lrow = t >> 2;
    const int lk4  = (t & 3) << 2;

    float acc[4][4];
#pragma unroll
    for (int i = 0; i < 4; i++)
#pragma unroll
        for (int j = 0; j < 4; j++) acc[i][j] = 0.f;

    for (int k0 = 0; k0 < K; k0 += 16) {
        float4 av = *(const float4*)(A + (size_t)(m0 + lrow) * lda + k0 + lk4);
        As[lk4 + 0][lrow] = av.x; As[lk4 + 1][lrow] = av.y;
        As[lk4 + 2][lrow] = av.z; As[lk4 + 3][lrow] = av.w;
        float4 bv = make_float4(0.f, 0.f, 0.f, 0.f);
        if (n0 + lrow < N)
            bv = *(const float4*)(B + (size_t)(n0 + lrow) * ldb + k0 + lk4);
        Bs[lk4 + 0][lrow] = bv.x; Bs[lk4 + 1][lrow] = bv.y;
        Bs[lk4 + 2][lrow] = bv.z; Bs[lk4 + 3][lrow] = bv.w;
        __syncthreads();
#pragma unroll
        for (int kk = 0; kk < 16; kk++) {
            float4 a  = *(const float4*)&As[kk][ty << 2];
            float4 bb = *(const float4*)&Bs[kk][tx << 2];
            float ar[4] = {a.x, a.y, a.z, a.w};
            float br[4] = {bb.x, bb.y, bb.z, bb.w};
#pragma unroll
            for (int i = 0; i < 4; i++)
#pragma unroll
                for (int j = 0; j < 4; j++) acc[i][j] += ar[i] * br[j];
        }
        __syncthreads();
    }

#pragma unroll
    for (int i = 0; i < 4; i++) {
        int m = m0 + (ty << 2) + i;
#pragma unroll
        for (int j = 0; j < 4; j++) {
            int n = n0 + (tx << 2) + j;
            if (n >= N) continue;
            float v = acc[i][j];
            if (MODE == 0) {
                C[(size_t)m * N + n] = v;
            } else if (MODE == 1) {
                int b = m >> 11, l = m & 2047;
                if (n < DINNER) C[((size_t)b * DINNER + n) * LSEQ + l] = v;
                else            aux[((size_t)b * LSEQ + l) * DINNER + (n - DINNER)] = v;
            } else {
                float x = v + bias[n];
                C[(size_t)m * N + n] = (x > 20.f) ? x : log1pf(expf(x));
            }
        }
    }
}

// ---------------- FFT bands / features ---------------------------------------
__global__ __launch_bounds__(256)
void bands_kernel()
{
    int gid = blockIdx.x * blockDim.x + threadIdx.x;   // 65536
    int c  = gid & 2047;
    int fr = gid >> 11;                                // 0..31
    int b  = fr >> 3, tt = fr & 7;

    const float* px = g_xcl + ((size_t)b * DINNER + c) * LSEQ + tt * (HH * WW);
    float X[HH * WW];
#pragma unroll 1
    for (int i = 0; i < HH * WW; i++) X[i] = px[i];

    double bands[8];
#pragma unroll
    for (int k = 0; k < 8; k++) bands[k] = 0.0;

#pragma unroll 1
    for (int v = 0; v < 9; v++) {
        float Rre[16], Rim[16];
#pragma unroll
        for (int h = 0; h < 16; h++) {
            float re = 0.f, im = 0.f;
#pragma unroll
            for (int w = 0; w < 16; w++) {
                int ph = (v * w) & 15;
                float xv = X[h * 16 + w];
                re += xv * c_ct[ph];
                im -= xv * c_st[ph];
            }
            Rre[h] = re; Rim[h] = im;
        }
        // fftshift along width (n=9): original freq v lands at index (v+4)%9
        int jj = (v + 4) % 9;
        float dw = (float)(jj - 4) / 9.0f;
        float dw2 = dw * dw;
#pragma unroll 1
        for (int u = 0; u < 16; u++) {
            float Fre = 0.f, Fim = 0.f;
#pragma unroll
            for (int h = 0; h < 16; h++) {
                int ph = (u * h) & 15;
                float cr = c_ct[ph], sr = c_st[ph];
                Fre += Rre[h] * cr + Rim[h] * sr;
                Fim += Rim[h] * cr - Rre[h] * sr;
            }
            float mag = sqrtf(Fre * Fre + Fim * Fim + 1e-8f);
            // fftshift along height (n=16): original freq u lands at (u+8)%16
            int i2 = (u + 8) & 15;
            float dh = (float)(i2 - 8) / 16.0f;
            float r = sqrtf(dh * dh + dw2);
            int band = (int)(r * 8.0f);
            if (band > 7) band = 7;
            bands[band] += (double)mag;
        }
    }
    double tot = 0.0;
#pragma unroll
    for (int k = 0; k < 8; k++) tot += bands[k];
    double inv = 1.0 / (tot + 1e-8);
    g_feat[(size_t)fr * DINNER + c] =
        (float)((bands[4] + bands[5] + bands[6] + bands[7]) * inv);
}

// ---------------- loss = 1 - ||sum_f fn_f||^2 / (32*32) ----------------------
__global__ __launch_bounds__(256)
void loss_kernel(float* __restrict__ out, int out_size)
{
    __shared__ double red[256];
    __shared__ double invn[NFR];
    int tid = threadIdx.x;
    for (int fr = 0; fr < NFR; fr++) {
        double s = 0.0;
        for (int c = tid; c < DINNER; c += 256) {
            double v = (double)g_feat[fr * DINNER + c];
            s += v * v;
        }
        red[tid] = s; __syncthreads();
        for (int o = 128; o > 0; o >>= 1) {
            if (tid < o) red[tid] += red[tid + o];
            __syncthreads();
        }
        if (tid == 0) invn[fr] = 1.0 / fmax(sqrt(red[0]), 1e-12);
        __syncthreads();
    }
    double s = 0.0;
    for (int c = tid; c < DINNER; c += 256) {
        double gsum = 0.0;
        for (int fr = 0; fr < NFR; fr++) gsum += (double)g_feat[fr * DINNER + c] * invn[fr];
        s += gsum * gsum;
    }
    red[tid] = s; __syncthreads();
    for (int o = 128; o > 0; o >>= 1) {
        if (tid < o) red[tid] += red[tid + o];
        __syncthreads();
    }
    if (tid == 0) {
        float loss = (float)(1.0 - red[0] / (double)(NFR * NFR));
        for (int i = NOUT; i < out_size; i++) out[i] = loss;
    }
}

// ---------------- f = softmax(mean_f features) --------------------------------
__global__ __launch_bounds__(256)
void fsoftmax_kernel()
{
    __shared__ float red[256];
    int tid = threadIdx.x;
    float lmax = -1e30f;
    for (int c = tid; c < DINNER; c += 256) {
        float s = 0.f;
        for (int fr = 0; fr < NFR; fr++) s += g_feat[fr * DINNER + c];
        float mu = s / (float)NFR;
        g_f[c] = mu;
        lmax = fmaxf(lmax, mu);
    }
    red[tid] = lmax; __syncthreads();
    for (int o = 128; o > 0; o >>= 1) {
        if (tid < o) red[tid] = fmaxf(red[tid], red[tid + o]);
        __syncthreads();
    }
    float mx = red[0]; __syncthreads();
    float lsum = 0.f;
    for (int c = tid; c < DINNER; c += 256) lsum += expf(g_f[c] - mx);
    red[tid] = lsum; __syncthreads();
    for (int o = 128; o > 0; o >>= 1) {
        if (tid < o) red[tid] += red[tid + o];
        __syncthreads();
    }
    float tot = red[0]; __syncthreads();
    for (int c = tid; c < DINNER; c += 256) g_f[c] = expf(g_f[c] - mx) / tot;
}

// ---------------- A stats: attention, column max/min --------------------------
__global__ __launch_bounds__(256)
void astats_kernel(const float* __restrict__ A_log)
{
    __shared__ float red[256];
    int tid = threadIdx.x;
    float lmax = 0.f;
    for (int d = tid; d < DINNER; d += 256) {
        float s = 0.f;
        for (int n = 0; n < DSTATE; n++) {
            float e = expf(A_log[d * DSTATE + n]);
            s += e * e;
        }
        float a = sqrtf(s);
        g_att[d] = a;
        lmax = fmaxf(lmax, a);
    }
    red[tid] = lmax; __syncthreads();
    for (int o = 128; o > 0; o >>= 1) {
        if (tid < o) red[tid] = fmaxf(red[tid], red[tid + o]);
        __syncthreads();
    }
    if (tid == 0) g_attmax = red[0];
    if (tid < DSTATE) {
        float mx = -1e30f, mn = 1e30f;
        for (int d = 0; d < DINNER; d++) {
            float v = A_log[d * DSTATE + tid];
            mx = fmaxf(mx, v); mn = fminf(mn, v);
        }
        g_Amax[tid] = mx; g_Amin[tid] = mn;
    }
}

// ---------------- A = -exp(blend(A_log)) --------------------------------------
__global__ __launch_bounds__(256)
void acompute_kernel(const float* __restrict__ A_log)
{
    int idx = blockIdx.x * blockDim.x + threadIdx.x;
    if (idx >= DINNER * DSTATE) return;
    int d = idx >> 4, n = idx & 15;
    float attn = g_att[d] / (g_attmax + 1e-8f);
    float alpha = fminf(fmaxf(g_f[d] * (1.f - attn), 0.f), 1.f);
    float al = A_log[idx];
    float anew = (1.f - alpha) * al + alpha * (g_Amax[n] + g_Amin[n] - al);
    g_A[idx] = -expf(anew);
}

// ---------------- depthwise causal conv + silu, with transpose ----------------
__global__ __launch_bounds__(256)
void conv_kernel(const float* __restrict__ w, const float* __restrict__ bias)
{
    __shared__ float sx[32][36];
    __shared__ float so[32][33];
    int b = blockIdx.z, d0 = blockIdx.y * 32, l0 = blockIdx.x * 32;
    int tx = threadIdx.x, ty = threadIdx.y;

    for (int i = ty; i < 32; i += 8) {
        int d = d0 + i;
        const float* row = g_xcl + ((size_t)b * DINNER + d) * LSEQ;
        int l = l0 - 3 + tx;
        sx[i][tx] = (l >= 0) ? row[l] : 0.f;
        if (tx < 3) sx[i][32 + tx] = row[l0 + 29 + tx];
    }
    __syncthreads();
    for (int i = ty; i < 32; i += 8) {
        int d = d0 + i;
        float w0 = w[d * 4 + 0], w1 = w[d * 4 + 1], w2 = w[d * 4 + 2], w3 = w[d * 4 + 3];
        float v = sx[i][tx] * w0 + sx[i][tx + 1] * w1 + sx[i][tx + 2] * w2
                + sx[i][tx + 3] * w3 + bias[d];
        so[tx][i] = v / (1.f + expf(-v));
    }
    __syncthreads();
    for (int i = ty; i < 32; i += 8) {
        int l = l0 + i;
        g_xct[((size_t)b * LSEQ + l) * DINNER + d0 + tx] = so[i][tx];
    }
}

// ---------------- selective scan: thread per (b, d, n) ------------------------
__global__ __launch_bounds__(256)
void scan_kernel(const float* __restrict__ Dp)
{
    int gid = blockIdx.x * blockDim.x + threadIdx.x;  // 131072
    int grp = gid >> 4;
    int n = gid & 15;
    int b = grp >> 11;
    int d = grp & 2047;

    float a  = g_A[d * DSTATE + n];
    float Dd = Dp[d];
    const float* dptr  = g_delta + (size_t)b * LSEQ * DINNER + d;
    const float* uptr  = g_xct   + (size_t)b * LSEQ * DINNER + d;
    const float* zptr  = g_zt    + (size_t)b * LSEQ * DINNER + d;
    const float* bcptr = g_xdbl  + (size_t)b * LSEQ * XDBLW;
    float*       yptr  = g_y     + (size_t)b * LSEQ * DINNER + d;

    float s = 0.f;
    for (int l = 0; l < LSEQ; l++) {
        float dt = dptr[(size_t)l * DINNER];
        float u  = uptr[(size_t)l * DINNER];
        float Bn = bcptr[l * XDBLW + DTRANK + n];
        float Cn = bcptr[l * XDBLW + DTRANK + DSTATE + n];
        s = s * expf(dt * a) + dt * u * Bn;
        float p = s * Cn;
        p += __shfl_xor_sync(0xffffffffu, p, 1);
        p += __shfl_xor_sync(0xffffffffu, p, 2);
        p += __shfl_xor_sync(0xffffffffu, p, 4);
        p += __shfl_xor_sync(0xffffffffu, p, 8);
        if (n == 0) {
            float zv = zptr[(size_t)l * DINNER];
            float sil = zv / (1.f + expf(-zv));
            yptr[(size_t)l * DINNER] = (p + u * Dd) * sil;
        }
    }
}

// ---------------- launch --------------------------------------------------------
extern "C" void kernel_launch(void* const* d_in, const int* in_sizes, int n_in,
                              void* d_out, int out_size)
{
    int off = (n_in >= 13) ? 4 : 1;
    const float* hs    = (const float*)d_in[0];
    const float* inw   = (const float*)d_in[off + 0];
    const float* convw = (const float*)d_in[off + 1];
    const float* convb = (const float*)d_in[off + 2];
    const float* xpw   = (const float*)d_in[off + 3];
    const float* dtw   = (const float*)d_in[off + 4];
    const float* dtb   = (const float*)d_in[off + 5];
    const float* Alog  = (const float*)d_in[off + 6];
    const float* Dp    = (const float*)d_in[off + 7];
    const float* outw  = (const float*)d_in[off + 8];
    float* out = (float*)d_out;

    float *p_xcl, *p_zt, *p_xct, *p_delta, *p_y, *p_xdbl;
    cudaGetSymbolAddress((void**)&p_xcl,   g_xcl);
    cudaGetSymbolAddress((void**)&p_zt,    g_zt);
    cudaGetSymbolAddress((void**)&p_xct,   g_xct);
    cudaGetSymbolAddress((void**)&p_delta, g_delta);
    cudaGetSymbolAddress((void**)&p_y,     g_y);
    cudaGetSymbolAddress((void**)&p_xdbl,  g_xdbl);

    // 1. in_proj: (8192,1024) x (4096,1024)^T -> x_cl + z_t
    gemm_nt<1><<<dim3(4096 / 64, NTOK / 64), 256>>>(
        hs, DMODEL, inw, DMODEL, p_xcl, NTOK, 2 * DINNER, DMODEL, nullptr, p_zt);

    // 2. FFT bands -> features
    bands_kernel<<<(NFR * DINNER) / 256, 256>>>();

    // 3. loss (writes tail of d_out), softmax f, A stats, A blend
    loss_kernel<<<1, 256>>>(out, out_size);
    fsoftmax_kernel<<<1, 256>>>();
    astats_kernel<<<1, 256>>>(Alog);
    acompute_kernel<<<(DINNER * DSTATE + 255) / 256, 256>>>(Alog);

    // 4. depthwise conv + silu (-> xct transposed)
    conv_kernel<<<dim3(LSEQ / 32, DINNER / 32, BSZ), dim3(32, 8)>>>(convw, convb);

    // 5. x_proj: (8192,2048) x (96,2048)^T -> x_dbl
    gemm_nt<0><<<dim3(2, NTOK / 64), 256>>>(
        p_xct, DINNER, xpw, DINNER, p_xdbl, NTOK, XDBLW, DINNER, nullptr, nullptr);

    // 6. dt_proj + softplus: (8192,64) x (2048,64)^T -> delta
    gemm_nt<2><<<dim3(DINNER / 64, NTOK / 64), 256>>>(
        p_xdbl, XDBLW, dtw, DTRANK, p_delta, NTOK, DINNER, DTRANK, dtb, nullptr);

    // 7. selective scan -> y
    scan_kernel<<<(BSZ * DINNER * DSTATE) / 256, 256>>>(Dp);

    // 8. out_proj: (8192,2048) x (1024,2048)^T -> out
    gemm_nt<0><<<dim3(DMODEL / 64, NTOK / 64), 256>>>(
        p_y, DINNER, outw, DINNER, out, NTOK, DMODEL, DINNER, nullptr, nullptr);
}

// round 14
// speedup vs baseline: 1.8345x; 1.8345x over previous
#include <cuda_runtime.h>
#include <cuda_bf16.h>
#include <cstdint>
#include <math.h>

#define BSZ    4
#define LSEQ   2048
#define DMODEL 1024
#define DINNER 2048
#define DSTATE 16
#define DTRANK 64
#define NTOK   (BSZ*LSEQ)        // 8192
#define TT     8
#define HH     16
#define WW     16
#define NFR    (BSZ*TT)          // 32
#define XDBLW  96
#define NOUT   (BSZ*LSEQ*DMODEL) // 8388608

// ---------------- scratch (static device globals; no allocation) -------------
__device__ float g_xcl [BSZ*DINNER*LSEQ];   // x (B, D, L) channel-major
__device__ float g_zt  [BSZ*DINNER*LSEQ];   // z (B, D, L) channel-major
__device__ float g_xct [BSZ*DINNER*LSEQ];   // conv(x) silu (B, D, L) channel-major
__device__ float g_delta[BSZ*DINNER*LSEQ];  // (B, D, L) channel-major
__device__ float g_y   [BSZ*DINNER*LSEQ];   // (B, D, L) channel-major
__device__ float g_xdbl[NTOK*XDBLW];        // (B*L, 96)
__device__ float g_feat[NFR*DINNER];
__device__ float g_f   [DINNER];
__device__ float g_att [DINNER];
__device__ float g_attmax;
__device__ float g_Amax[DSTATE];
__device__ float g_Amin[DSTATE];
__device__ float g_A   [DINNER*DSTATE];

// bf16 split operands: A-side [hi,hi,lo], B-side [hi,lo,hi]
__device__ __nv_bfloat16 g_a_hs [(size_t)NTOK*3*DMODEL];   // 8192 x 3072
__device__ __nv_bfloat16 g_a_x  [(size_t)NTOK*3*DINNER];   // 8192 x 6144
__device__ __nv_bfloat16 g_a_dt [(size_t)NTOK*3*DTRANK];   // 8192 x 192
__device__ __nv_bfloat16 g_a_y  [(size_t)NTOK*3*DINNER];   // 8192 x 6144
__device__ __nv_bfloat16 g_w_in [(size_t)(2*DINNER)*3*DMODEL]; // 4096 x 3072
__device__ __nv_bfloat16 g_w_x  [(size_t)128*3*DINNER];        // 128 x 6144 (96 padded)
__device__ __nv_bfloat16 g_w_dt [(size_t)DINNER*3*DTRANK];     // 2048 x 192
__device__ __nv_bfloat16 g_w_out[(size_t)DMODEL*3*DINNER];     // 1024 x 6144

// exact twiddles: cos/sin(2*pi*k/16)
__constant__ float c_ct[16] = {
    1.0f, 0.92387953251128674f, 0.70710678118654752f, 0.38268343236508978f,
    0.0f, -0.38268343236508978f, -0.70710678118654752f, -0.92387953251128674f,
    -1.0f, -0.92387953251128674f, -0.70710678118654752f, -0.38268343236508978f,
    0.0f, 0.38268343236508978f, 0.70710678118654752f, 0.92387953251128674f};
__constant__ float c_st[16] = {
    0.0f, 0.38268343236508978f, 0.70710678118654752f, 0.92387953251128674f,
    1.0f, 0.92387953251128674f, 0.70710678118654752f, 0.38268343236508978f,
    0.0f, -0.38268343236508978f, -0.70710678118654752f, -0.92387953251128674f,
    -1.0f, -0.92387953251128674f, -0.70710678118654752f, -0.38268343236508978f};

// ================== split conversion: fp32 -> bf16 triple ====================
// PAT 0 (A-side): [hi, hi, lo]   PAT 1 (B-side): [hi, lo, hi]
template<int PAT>
__global__ __launch_bounds__(256)
void split_rows(const float* __restrict__ src, int lda, int rows, int K,
                __nv_bfloat16* __restrict__ dst, int rows_pad)
{
    int idx = blockIdx.x * 256 + threadIdx.x;
    if (idx >= rows_pad * K) return;
    int r = idx / K, k = idx - r * K;
    float v = (r < rows) ? src[(size_t)r * lda + k] : 0.f;
    __nv_bfloat16 hi = __float2bfloat16(v);
    __nv_bfloat16 lo = __float2bfloat16(v - __bfloat162float(hi));
    __nv_bfloat16* o = dst + (size_t)r * 3 * K;
    if (PAT == 0) { o[k] = hi; o[K + k] = hi; o[2 * K + k] = lo; }
    else          { o[k] = hi; o[K + k] = lo; o[2 * K + k] = hi; }
}

// transpose-split: channel-major [b][d][l] fp32 -> A' [(b*L+l)][3*DINNER] [hi,hi,lo]
__global__ __launch_bounds__(256)
void split_trans(const float* __restrict__ src, __nv_bfloat16* __restrict__ dst)
{
    __shared__ float tile[32][33];
    int b = blockIdx.z, d0 = blockIdx.y * 32, l0 = blockIdx.x * 32;
    int tx = threadIdx.x, ty = threadIdx.y;
    for (int i = ty; i < 32; i += 8)
        tile[i][tx] = src[((size_t)b * DINNER + d0 + i) * LSEQ + l0 + tx];
    __syncthreads();
    for (int i = ty; i < 32; i += 8) {
        int l = l0 + i, d = d0 + tx;
        float v = tile[tx][i];
        __nv_bfloat16 hi = __float2bfloat16(v);
        __nv_bfloat16 lo = __float2bfloat16(v - __bfloat162float(hi));
        __nv_bfloat16* o = dst + ((size_t)b * LSEQ + l) * (3 * DINNER);
        o[d] = hi; o[DINNER + d] = hi; o[2 * DINNER + d] = lo;
    }
}

// ==================== warp-mma GEMM: C[m,n] = sum A'[m,k]B'[n,k] =============
// CTA tile M=128 x N=64, K chunks of 32 bf16, 256 threads (8 warps, 4x2).
// mma.sync.m16n8k16 bf16 -> f32. cp.async double-buffered smem.
// MODE 0: C[m*ldc+n] = v (n < Nreal)
// MODE 1: in_proj split -> g_xcl / aux(z), channel-major
// MODE 2: delta = softplus(v + bias[n]) -> C, channel-major
#define AST 20   // u32 stride per smem row (conflict-free for frag loads)

__device__ __forceinline__ uint32_t smem_to_u32(const void* p) {
    uint32_t a;
    asm("{ .reg .u64 t; cvta.to.shared.u64 t, %1; cvt.u32.u64 %0, t; }"
        : "=r"(a) : "l"(p));
    return a;
}
#define CP_ASYNC16(dst, src) \
    asm volatile("cp.async.cg.shared.global [%0], [%1], 16;" \
                 :: "r"(dst), "l"(src) : "memory")
#define CP_COMMIT() asm volatile("cp.async.commit_group;" ::: "memory")
#define CP_WAIT1()  asm volatile("cp.async.wait_group 1;" ::: "memory")

__device__ __forceinline__ void mma16816(float* c, const uint32_t* a, const uint32_t* b) {
    asm volatile(
        "mma.sync.aligned.m16n8k16.row.col.f32.bf16.bf16.f32 "
        "{%0,%1,%2,%3}, {%4,%5,%6,%7}, {%8,%9}, {%0,%1,%2,%3};"
        : "+f"(c[0]), "+f"(c[1]), "+f"(c[2]), "+f"(c[3])
        : "r"(a[0]), "r"(a[1]), "r"(a[2]), "r"(a[3]), "r"(b[0]), "r"(b[1]));
}

template<int MODE>
__global__ __launch_bounds__(256)
void mma_nt(const __nv_bfloat16* __restrict__ Abf, int ldaP,
            const __nv_bfloat16* __restrict__ Bbf, int ldbP,
            float* __restrict__ C, int ldc, int Nreal, int KP,
            const float* __restrict__ bias, float* __restrict__ aux)
{
    __shared__ __align__(16) uint32_t As[2][128 * AST];
    __shared__ __align__(16) uint32_t Bs[2][64 * AST];
    const int t = threadIdx.x;
    const int lane = t & 31, w = t >> 5;
    const int wm = (w >> 1) * 32, wn = (w & 1) * 32;
    const int m0 = blockIdx.y * 128, n0 = blockIdx.x * 64;
    const int ar = t >> 2, aq = t & 3;       // 64 rows x 4 quads

    const uint32_t as_u = smem_to_u32(As);
    const uint32_t bs_u = smem_to_u32(Bs);

    float acc[2][4][4];
#pragma unroll
    for (int i = 0; i < 2; i++)
#pragma unroll
        for (int j = 0; j < 4; j++)
#pragma unroll
            for (int k = 0; k < 4; k++) acc[i][j][k] = 0.f;

    const int niter = KP >> 5;   // BK = 32

    // prefetch tile 0 into buf 0
    {
        const int kb = 0;
        CP_ASYNC16(as_u + (uint32_t)((0 * 128 + ar) * AST + aq * 4) * 4,
                   Abf + (size_t)(m0 + ar) * ldaP + kb + aq * 8);
        CP_ASYNC16(as_u + (uint32_t)((0 * 128 + 64 + ar) * AST + aq * 4) * 4,
                   Abf + (size_t)(m0 + 64 + ar) * ldaP + kb + aq * 8);
        CP_ASYNC16(bs_u + (uint32_t)((0 * 64 + ar) * AST + aq * 4) * 4,
                   Bbf + (size_t)(n0 + ar) * ldbP + kb + aq * 8);
        CP_COMMIT();
    }

    for (int it = 0; it < niter; it++) {
        const int buf = it & 1;
        if (it + 1 < niter) {
            const int nb = buf ^ 1, kb = (it + 1) << 5;
            CP_ASYNC16(as_u + (uint32_t)((nb * 128 + ar) * AST + aq * 4) * 4,
                       Abf + (size_t)(m0 + ar) * ldaP + kb + aq * 8);
            CP_ASYNC16(as_u + (uint32_t)((nb * 128 + 64 + ar) * AST + aq * 4) * 4,
                       Abf + (size_t)(m0 + 64 + ar) * ldaP + kb + aq * 8);
            CP_ASYNC16(bs_u + (uint32_t)((nb * 64 + ar) * AST + aq * 4) * 4,
                       Bbf + (size_t)(n0 + ar) * ldbP + kb + aq * 8);
        }
        CP_COMMIT();
        CP_WAIT1();
        __syncthreads();

        const uint32_t* Ab = As[buf];
        const uint32_t* Bb = Bs[buf];
#pragma unroll
        for (int ks = 0; ks < 2; ks++) {
            const int kc = ks * 8;
            uint32_t afr[2][4];
#pragma unroll
            for (int mt = 0; mt < 2; mt++) {
                int r = wm + mt * 16 + (lane >> 2);
                afr[mt][0] = Ab[r * AST + kc + (lane & 3)];
                afr[mt][1] = Ab[(r + 8) * AST + kc + (lane & 3)];
                afr[mt][2] = Ab[r * AST + kc + 4 + (lane & 3)];
                afr[mt][3] = Ab[(r + 8) * AST + kc + 4 + (lane & 3)];
            }
            uint32_t bfr[4][2];
#pragma unroll
            for (int nt = 0; nt < 4; nt++) {
                int rn = wn + nt * 8 + (lane >> 2);
                bfr[nt][0] = Bb[rn * AST + kc + (lane & 3)];
                bfr[nt][1] = Bb[rn * AST + kc + 4 + (lane & 3)];
            }
#pragma unroll
            for (int mt = 0; mt < 2; mt++)
#pragma unroll
                for (int nt = 0; nt < 4; nt++)
                    mma16816(acc[mt][nt], afr[mt], bfr[nt]);
        }
        __syncthreads();
    }

    // epilogue
#pragma unroll
    for (int mt = 0; mt < 2; mt++) {
#pragma unroll
        for (int nt = 0; nt < 4; nt++) {
            int mb = m0 + wm + mt * 16 + (lane >> 2);
            int nb = n0 + wn + nt * 8 + (lane & 3) * 2;
#pragma unroll
            for (int e = 0; e < 4; e++) {
                int m = mb + (e >> 1) * 8;
                int n = nb + (e & 1);
                float v = acc[mt][nt][e];
                if (MODE == 0) {
                    if (n < Nreal) C[(size_t)m * ldc + n] = v;
                } else if (MODE == 1) {
                    int b = m >> 11, l = m & 2047;
                    if (n < DINNER)
                        g_xcl[((size_t)b * DINNER + n) * LSEQ + l] = v;
                    else
                        aux[((size_t)b * DINNER + (n - DINNER)) * LSEQ + l] = v;
                } else {
                    int b = m >> 11, l = m & 2047;
                    float x = v + bias[n];
                    float sp = (x > 20.f) ? x : log1pf(__expf(x));
                    C[((size_t)b * DINNER + n) * LSEQ + l] = sp;
                }
            }
        }
    }
}

// ---------------- FFT bands / features ---------------------------------------
__global__ __launch_bounds__(256)
void bands_kernel()
{
    int gid = blockIdx.x * blockDim.x + threadIdx.x;   // 65536
    int c  = gid & 2047;
    int fr = gid >> 11;
    int b  = fr >> 3, tt = fr & 7;

    const float* px = g_xcl + ((size_t)b * DINNER + c) * LSEQ + tt * (HH * WW);
    float X[HH * WW];
#pragma unroll 1
    for (int i = 0; i < HH * WW; i++) X[i] = px[i];

    double bands[8];
#pragma unroll
    for (int k = 0; k < 8; k++) bands[k] = 0.0;

#pragma unroll 1
    for (int v = 0; v < 9; v++) {
        float Rre[16], Rim[16];
#pragma unroll
        for (int h = 0; h < 16; h++) {
            float re = 0.f, im = 0.f;
#pragma unroll
            for (int w = 0; w < 16; w++) {
                int ph = (v * w) & 15;
                float xv = X[h * 16 + w];
                re += xv * c_ct[ph];
                im -= xv * c_st[ph];
            }
            Rre[h] = re; Rim[h] = im;
        }
        int jj = (v + 4) % 9;                 // fftshift width (n=9)
        float dw = (float)(jj - 4) / 9.0f;
        float dw2 = dw * dw;
#pragma unroll 1
        for (int u = 0; u < 16; u++) {
            float Fre = 0.f, Fim = 0.f;
#pragma unroll
            for (int h = 0; h < 16; h++) {
                int ph = (u * h) & 15;
                float cr = c_ct[ph], sr = c_st[ph];
                Fre += Rre[h] * cr + Rim[h] * sr;
                Fim += Rim[h] * cr - Rre[h] * sr;
            }
            float mag = sqrtf(Fre * Fre + Fim * Fim + 1e-8f);
            int i2 = (u + 8) & 15;            // fftshift height (n=16)
            float dh = (float)(i2 - 8) / 16.0f;
            float rr = sqrtf(dh * dh + dw2);
            int band = (int)(rr * 8.0f);
            if (band > 7) band = 7;
            bands[band] += (double)mag;
        }
    }
    double tot = 0.0;
#pragma unroll
    for (int k = 0; k < 8; k++) tot += bands[k];
    double inv = 1.0 / (tot + 1e-8);
    g_feat[(size_t)fr * DINNER + c] =
        (float)((bands[4] + bands[5] + bands[6] + bands[7]) * inv);
}

// ---------------- loss ----------------------------------------------------------
__global__ __launch_bounds__(256)
void loss_kernel(float* __restrict__ out, int out_size)
{
    __shared__ double red[256];
    __shared__ double invn[NFR];
    int tid = threadIdx.x;
    for (int fr = 0; fr < NFR; fr++) {
        double s = 0.0;
        for (int c = tid; c < DINNER; c += 256) {
            double v = (double)g_feat[fr * DINNER + c];
            s += v * v;
        }
        red[tid] = s; __syncthreads();
        for (int o = 128; o > 0; o >>= 1) {
            if (tid < o) red[tid] += red[tid + o];
            __syncthreads();
        }
        if (tid == 0) invn[fr] = 1.0 / fmax(sqrt(red[0]), 1e-12);
        __syncthreads();
    }
    double s = 0.0;
    for (int c = tid; c < DINNER; c += 256) {
        double gsum = 0.0;
        for (int fr = 0; fr < NFR; fr++) gsum += (double)g_feat[fr * DINNER + c] * invn[fr];
        s += gsum * gsum;
    }
    red[tid] = s; __syncthreads();
    for (int o = 128; o > 0; o >>= 1) {
        if (tid < o) red[tid] += red[tid + o];
        __syncthreads();
    }
    if (tid == 0) {
        float loss = (float)(1.0 - red[0] / (double)(NFR * NFR));
        for (int i = NOUT; i < out_size; i++) out[i] = loss;
    }
}

// ---------------- f = softmax(mean features) -----------------------------------
__global__ __launch_bounds__(256)
void fsoftmax_kernel()
{
    __shared__ float red[256];
    int tid = threadIdx.x;
    float lmax = -1e30f;
    for (int c = tid; c < DINNER; c += 256) {
        float s = 0.f;
        for (int fr = 0; fr < NFR; fr++) s += g_feat[fr * DINNER + c];
        float mu = s / (float)NFR;
        g_f[c] = mu;
        lmax = fmaxf(lmax, mu);
    }
    red[tid] = lmax; __syncthreads();
    for (int o = 128; o > 0; o >>= 1) {
        if (tid < o) red[tid] = fmaxf(red[tid], red[tid + o]);
        __syncthreads();
    }
    float mx = red[0]; __syncthreads();
    float lsum = 0.f;
    for (int c = tid; c < DINNER; c += 256) lsum += expf(g_f[c] - mx);
    red[tid] = lsum; __syncthreads();
    for (int o = 128; o > 0; o >>= 1) {
        if (tid < o) red[tid] += red[tid + o];
        __syncthreads();
    }
    float tot = red[0]; __syncthreads();
    for (int c = tid; c < DINNER; c += 256) g_f[c] = expf(g_f[c] - mx) / tot;
}

// ---------------- A stats -------------------------------------------------------
__global__ __launch_bounds__(256)
void astats_kernel(const float* __restrict__ A_log)
{
    __shared__ float red[256];
    int tid = threadIdx.x;
    float lmax = 0.f;
    for (int d = tid; d < DINNER; d += 256) {
        float s = 0.f;
        for (int n = 0; n < DSTATE; n++) {
            float e = expf(A_log[d * DSTATE + n]);
            s += e * e;
        }
        float a = sqrtf(s);
        g_att[d] = a;
        lmax = fmaxf(lmax, a);
    }
    red[tid] = lmax; __syncthreads();
    for (int o = 128; o > 0; o >>= 1) {
        if (tid < o) red[tid] = fmaxf(red[tid], red[tid + o]);
        __syncthreads();
    }
    if (tid == 0) g_attmax = red[0];
    if (tid < DSTATE) {
        float mx = -1e30f, mn = 1e30f;
        for (int d = 0; d < DINNER; d++) {
            float v = A_log[d * DSTATE + tid];
            mx = fmaxf(mx, v); mn = fminf(mn, v);
        }
        g_Amax[tid] = mx; g_Amin[tid] = mn;
    }
}

// ---------------- A = -exp(blend(A_log)) ---------------------------------------
__global__ __launch_bounds__(256)
void acompute_kernel(const float* __restrict__ A_log)
{
    int idx = blockIdx.x * blockDim.x + threadIdx.x;
    if (idx >= DINNER * DSTATE) return;
    int d = idx >> 4, n = idx & 15;
    float attn = g_att[d] / (g_attmax + 1e-8f);
    float alpha = fminf(fmaxf(g_f[d] * (1.f - attn), 0.f), 1.f);
    float al = A_log[idx];
    float anew = (1.f - alpha) * al + alpha * (g_Amax[n] + g_Amin[n] - al);
    g_A[idx] = -expf(anew);
}

// ---------------- depthwise causal conv + silu (channel-major in & out) --------
__global__ __launch_bounds__(256)
void conv_kernel(const float* __restrict__ w, const float* __restrict__ bias)
{
    int l = blockIdx.x * 256 + threadIdx.x;
    int d = blockIdx.y, b = blockIdx.z;
    const float* row = g_xcl + ((size_t)b * DINNER + d) * LSEQ;
    float w0 = w[d * 4 + 0], w1 = w[d * 4 + 1], w2 = w[d * 4 + 2], w3 = w[d * 4 + 3];
    float x0 = (l >= 3) ? row[l - 3] : 0.f;
    float x1 = (l >= 2) ? row[l - 2] : 0.f;
    float x2 = (l >= 1) ? row[l - 1] : 0.f;
    float x3 = row[l];
    float v = x0 * w0 + x1 * w1 + x2 * w2 + x3 * w3 + bias[d];
    g_xct[((size_t)b * DINNER + d) * LSEQ + l] = v / (1.f + __expf(-v));
}

// ---------------- selective scan: thread per (b, d, n) -------------------------
__global__ __launch_bounds__(256)
void scan_kernel(const float* __restrict__ Dp)
{
    int gid = blockIdx.x * blockDim.x + threadIdx.x;  // 131072
    int grp = gid >> 4;
    int n = gid & 15;
    int b = grp >> 11;
    int d = grp & 2047;

    float a  = g_A[d * DSTATE + n];
    float Dd = Dp[d];
    size_t base = ((size_t)b * DINNER + d) * LSEQ;
    const float* dptr  = g_delta + base;
    const float* uptr  = g_xct   + base;
    const float* zptr  = g_zt    + base;
    const float* bcptr = g_xdbl  + (size_t)b * LSEQ * XDBLW;
    float*       yptr  = g_y     + base;

    float s = 0.f;
    for (int l = 0; l < LSEQ; l++) {
        float dt = dptr[l];
        float u  = uptr[l];
        float Bn = bcptr[l * XDBLW + DTRANK + n];
        float Cn = bcptr[l * XDBLW + DTRANK + DSTATE + n];
        s = s * __expf(dt * a) + dt * u * Bn;
        float p = s * Cn;
        p += __shfl_xor_sync(0xffffffffu, p, 1);
        p += __shfl_xor_sync(0xffffffffu, p, 2);
        p += __shfl_xor_sync(0xffffffffu, p, 4);
        p += __shfl_xor_sync(0xffffffffu, p, 8);
        if (n == 0) {
            float zv = zptr[l];
            float sil = zv / (1.f + __expf(-zv));
            yptr[l] = (p + u * Dd) * sil;
        }
    }
}

// ---------------- launch --------------------------------------------------------
extern "C" void kernel_launch(void* const* d_in, const int* in_sizes, int n_in,
                              void* d_out, int out_size)
{
    int off = (n_in >= 13) ? 4 : 1;
    const float* hs    = (const float*)d_in[0];
    const float* inw   = (const float*)d_in[off + 0];
    const float* convw = (const float*)d_in[off + 1];
    const float* convb = (const float*)d_in[off + 2];
    const float* xpw   = (const float*)d_in[off + 3];
    const float* dtw   = (const float*)d_in[off + 4];
    const float* dtb   = (const float*)d_in[off + 5];
    const float* Alog  = (const float*)d_in[off + 6];
    const float* Dp    = (const float*)d_in[off + 7];
    const float* outw  = (const float*)d_in[off + 8];
    float* out = (float*)d_out;

    float *p_zt, *p_delta, *p_xct, *p_y, *p_xdbl, *p_xcl;
    cudaGetSymbolAddress((void**)&p_xcl,   g_xcl);
    cudaGetSymbolAddress((void**)&p_zt,    g_zt);
    cudaGetSymbolAddress((void**)&p_xct,   g_xct);
    cudaGetSymbolAddress((void**)&p_delta, g_delta);
    cudaGetSymbolAddress((void**)&p_y,     g_y);
    cudaGetSymbolAddress((void**)&p_xdbl,  g_xdbl);
    __nv_bfloat16 *p_a_hs, *p_a_x, *p_a_dt, *p_a_y, *p_w_in, *p_w_x, *p_w_dt, *p_w_out;
    cudaGetSymbolAddress((void**)&p_a_hs,  g_a_hs);
    cudaGetSymbolAddress((void**)&p_a_x,   g_a_x);
    cudaGetSymbolAddress((void**)&p_a_dt,  g_a_dt);
    cudaGetSymbolAddress((void**)&p_a_y,   g_a_y);
    cudaGetSymbolAddress((void**)&p_w_in,  g_w_in);
    cudaGetSymbolAddress((void**)&p_w_x,   g_w_x);
    cudaGetSymbolAddress((void**)&p_w_dt,  g_w_dt);
    cudaGetSymbolAddress((void**)&p_w_out, g_w_out);

    // ---- conversions: weights (B-side PAT1) and hs (A-side PAT0)
    split_rows<1><<<(4096 * 1024 + 255) / 256, 256>>>(inw, DMODEL, 4096, DMODEL, p_w_in, 4096);
    split_rows<1><<<(128 * 2048 + 255) / 256, 256>>>(xpw, DINNER, XDBLW, DINNER, p_w_x, 128);
    split_rows<1><<<(2048 * 64 + 255) / 256, 256>>>(dtw, DTRANK, DINNER, DTRANK, p_w_dt, DINNER);
    split_rows<1><<<(1024 * 2048 + 255) / 256, 256>>>(outw, DINNER, DMODEL, DINNER, p_w_out, DMODEL);
    split_rows<0><<<(NTOK * DMODEL + 255) / 256, 256>>>(hs, DMODEL, NTOK, DMODEL, p_a_hs, NTOK);

    // 1. in_proj: (8192 x 3072) x (4096 x 3072)^T -> x_cl + z (channel-major)
    mma_nt<1><<<dim3(4096 / 64, NTOK / 128), 256>>>(
        p_a_hs, 3 * DMODEL, p_w_in, 3 * DMODEL, nullptr, 0, 4096, 3 * DMODEL, nullptr, p_zt);

    // 2. FFT bands -> features; loss / softmax / A stats / A blend
    bands_kernel<<<(NFR * DINNER) / 256, 256>>>();
    loss_kernel<<<1, 256>>>(out, out_size);
    fsoftmax_kernel<<<1, 256>>>();
    astats_kernel<<<1, 256>>>(Alog);
    acompute_kernel<<<(DINNER * DSTATE + 255) / 256, 256>>>(Alog);

    // 3. depthwise conv + silu (channel-major)
    conv_kernel<<<dim3(LSEQ / 256, DINNER, BSZ), 256>>>(convw, convb);

    // 4. x_proj: xct -> A' (transpose split), then GEMM -> xdbl (token-major, ld 96)
    split_trans<<<dim3(LSEQ / 32, DINNER / 32, BSZ), dim3(32, 8)>>>(p_xct, p_a_x);
    mma_nt<0><<<dim3(128 / 64, NTOK / 128), 256>>>(
        p_a_x, 3 * DINNER, p_w_x, 3 * DINNER, p_xdbl, XDBLW, XDBLW, 3 * DINNER, nullptr, nullptr);

    // 5. dt_proj + softplus -> delta (channel-major)
    split_rows<0><<<(NTOK * DTRANK + 255) / 256, 256>>>(p_xdbl, XDBLW, NTOK, DTRANK, p_a_dt, NTOK);
    mma_nt<2><<<dim3(DINNER / 64, NTOK / 128), 256>>>(
        p_a_dt, 3 * DTRANK, p_w_dt, 3 * DTRANK, p_delta, 0, DINNER, 3 * DTRANK, dtb, nullptr);

    // 6. selective scan -> y (channel-major)
    scan_kernel<<<(BSZ * DINNER * DSTATE) / 256, 256>>>(Dp);

    // 7. out_proj: y -> A' (transpose split), GEMM -> out
    split_trans<<<dim3(LSEQ / 32, DINNER / 32, BSZ), dim3(32, 8)>>>(p_y, p_a_y);
    mma_nt<0><<<dim3(DMODEL / 64, NTOK / 128), 256>>>(
        p_a_y, 3 * DINNER, p_w_out, 3 * DINNER, out, DMODEL, DMODEL, 3 * DINNER, nullptr, nullptr);
}